// round 13
// baseline (speedup 1.0000x reference)
#include <cuda_runtime.h>
#include <cuda_fp16.h>
#include <math.h>
#include <stdint.h>

#define T_TOK 1024
#define HDIM  2048
#define NEXP  64
#define IDIM  768
#define TOPK  8

// ---------------- device scratch ----------------
__device__ int    g_count[NEXP];
__device__ int    g_entry[NEXP * T_TOK];           // token*8 + slot
__device__ float  g_wt   [NEXP * T_TOK];
__device__ __half g_act  [T_TOK * TOPK * IDIM];    // fp16 silu(g)*u*w, gathered
__device__ __half g_x16  [T_TOK * HDIM];           // fp16 copy of hidden_states

// ---------------- helpers ----------------
__device__ __forceinline__ uint32_t smem_u32(const void* p) {
    uint32_t a;
    asm("{ .reg .u64 t; cvta.to.shared.u64 t, %1; cvt.u32.u64 %0, t; }" : "=r"(a) : "l"(p));
    return a;
}
__device__ __forceinline__ void sts128(uint32_t a, uint32_t x, uint32_t y, uint32_t z, uint32_t w) {
    asm volatile("st.shared.v4.b32 [%0], {%1,%2,%3,%4};" :: "r"(a), "r"(x), "r"(y), "r"(z), "r"(w));
}
__device__ __forceinline__ void ldsm4(uint32_t& r0, uint32_t& r1, uint32_t& r2, uint32_t& r3, uint32_t a) {
    asm volatile("ldmatrix.sync.aligned.m8n8.x4.shared.b16 {%0,%1,%2,%3}, [%4];"
                 : "=r"(r0), "=r"(r1), "=r"(r2), "=r"(r3) : "r"(a));
}
__device__ __forceinline__ void ldsm4t(uint32_t& r0, uint32_t& r1, uint32_t& r2, uint32_t& r3, uint32_t a) {
    asm volatile("ldmatrix.sync.aligned.m8n8.x4.trans.shared.b16 {%0,%1,%2,%3}, [%4];"
                 : "=r"(r0), "=r"(r1), "=r"(r2), "=r"(r3) : "r"(a));
}
__device__ __forceinline__ void mma_h(float& c0, float& c1, float& c2, float& c3,
                                      uint32_t a0, uint32_t a1, uint32_t a2, uint32_t a3,
                                      uint32_t b0, uint32_t b1) {
    asm volatile("mma.sync.aligned.m16n8k16.row.col.f32.f16.f16.f32 "
                 "{%0,%1,%2,%3},{%4,%5,%6,%7},{%8,%9},{%0,%1,%2,%3};"
                 : "+f"(c0), "+f"(c1), "+f"(c2), "+f"(c3)
                 : "r"(a0), "r"(a1), "r"(a2), "r"(a3), "r"(b0), "r"(b1));
}
__device__ __forceinline__ void cvt2h(float4 f, uint32_t& h0, uint32_t& h1) {
    __half2 a = __floats2half2_rn(f.x, f.y);
    __half2 b = __floats2half2_rn(f.z, f.w);
    h0 = *(uint32_t*)&a; h1 = *(uint32_t*)&b;
}
// async copy: 16B global->shared, src-size 0 => zero-fill
__device__ __forceinline__ void cpa16(uint32_t saddr, const void* gaddr, uint32_t srcsz) {
    asm volatile("cp.async.cg.shared.global [%0], [%1], 16, %2;"
                 :: "r"(saddr), "l"(gaddr), "r"(srcsz) : "memory");
}
#define CP_COMMIT() asm volatile("cp.async.commit_group;" ::: "memory")
#define CP_WAIT0()  asm volatile("cp.async.wait_group 0;" ::: "memory")
#define CP_WAIT1()  asm volatile("cp.async.wait_group 1;" ::: "memory")

// ---------- smem geometry (BK = 64) ----------
// A slot: 128x64 fp16 as two 128x32 sub-tiles (row stride 80B each), 3 slots
// gateup B buf: g,u each 64x64 fp16 (row stride 144B) = 2*9216
// down   B buf: 64x128 fp16 (row stride 272B) = 17408
#define META      2048
#define A_SUB     10240                 // 128*80
#define A_SLOT    (2 * A_SUB)           // 20480
#define GU_B_OFF  (META + 3 * A_SLOT)   // 63488
#define GU_B_BUF  18432                 // 2*9216
#define GU_SMEM   (GU_B_OFF + 2 * GU_B_BUF)   // 100352
#define DN_B_OFF  (META + 3 * A_SLOT)
#define DN_B_BUF  17408                 // 64*272
#define DN_SMEM   (DN_B_OFF + 2 * DN_B_BUF)   // 98304

// ---------------- kernel 0: x -> fp16, fused counter reset ----------------
__global__ __launch_bounds__(256)
void xcvt_kernel(const float* __restrict__ x) {
    if (blockIdx.x == 0 && threadIdx.x < NEXP) g_count[threadIdx.x] = 0;
    int i = (blockIdx.x * 256 + threadIdx.x) * 8;
    float4 f0 = *(const float4*)(x + i);
    float4 f1 = *(const float4*)(x + i + 4);
    uint4 v;
    cvt2h(f0, v.x, v.y);
    cvt2h(f1, v.z, v.w);
    *(uint4*)(g_x16 + i) = v;
}

// ---------------- kernel 1: router GEMM + top-8 + bucket scatter ----------------
__global__ __launch_bounds__(256)
void router_kernel(const float* __restrict__ x, const float* __restrict__ gw) {
    __shared__ float As[16][17];
    __shared__ float Bs[16][68];
    __shared__ float Ls[16][68];

    const int t0  = blockIdx.x * 16;
    const int tid = threadIdx.x;
    const int tx  = tid & 15;
    const int ty  = tid >> 4;

    const int am = tid >> 4, ak = tid & 15;
    const int be = tid & 63, bk4 = (tid >> 6) * 4;

    float acc[4] = {0.f, 0.f, 0.f, 0.f};

    for (int k0 = 0; k0 < HDIM; k0 += 16) {
        As[ak][am] = x[(size_t)(t0 + am) * HDIM + k0 + ak];
        float4 bv = *(const float4*)(gw + (size_t)be * HDIM + k0 + bk4);
        Bs[bk4 + 0][be] = bv.x; Bs[bk4 + 1][be] = bv.y;
        Bs[bk4 + 2][be] = bv.z; Bs[bk4 + 3][be] = bv.w;
        __syncthreads();
#pragma unroll
        for (int kk = 0; kk < 16; kk++) {
            float a = As[kk][ty];
#pragma unroll
            for (int j = 0; j < 4; j++) acc[j] += a * Bs[kk][tx * 4 + j];
        }
        __syncthreads();
    }

#pragma unroll
    for (int j = 0; j < 4; j++) Ls[ty][tx * 4 + j] = acc[j];
    __syncthreads();

    if (tid < 16) {
        int   sel[TOPK];
        float sv [TOPK];
        unsigned long long mask = 0ull;
#pragma unroll
        for (int k = 0; k < TOPK; k++) {
            float best = -1e30f;
            int   be_  = 0;
            for (int e = 0; e < NEXP; e++) {
                if ((mask >> e) & 1ull) continue;
                float v = Ls[tid][e];
                if (v > best) { best = v; be_ = e; }
            }
            mask |= (1ull << be_);
            sel[k] = be_;
            sv[k]  = best;
        }
        float mx = sv[0];
        float s  = 0.f;
#pragma unroll
        for (int k = 0; k < TOPK; k++) { sv[k] = expf(sv[k] - mx); s += sv[k]; }
        float inv = 1.f / s;
#pragma unroll
        for (int k = 0; k < TOPK; k++) {
            int e   = sel[k];
            int pos = atomicAdd(&g_count[e], 1);
            g_entry[e * T_TOK + pos] = (t0 + tid) * TOPK + k;
            g_wt   [e * T_TOK + pos] = sv[k] * inv;
        }
    }
}

// ---------------- kernel 2: gate+up HMMA GEMM, BK=64, 3-slot A ring ----------------
__global__ __launch_bounds__(256, 2)
void gateup_mma(const float* __restrict__ wg,
                const float* __restrict__ wu) {
    extern __shared__ char smem[];
    const int e   = blockIdx.z;
    const int cnt = g_count[e];
    const int m0  = blockIdx.y * 128;
    if (m0 >= cnt) return;
    const int n0  = blockIdx.x * 64;
    const int tid  = threadIdx.x;
    const int wid  = tid >> 5;
    const int lane = tid & 31;

    const uint32_t sb = smem_u32(smem);
    int*   sEnt = (int*)smem;
    float* sW   = (float*)(smem + 1024);

    if (tid < 128) {
        int mi = m0 + tid;
        if (mi < cnt) { sEnt[tid] = g_entry[e * T_TOK + mi]; sW[tid] = g_wt[e * T_TOK + mi]; }
        else          { sEnt[tid] = -1;                      sW[tid] = 0.f; }
    }
    __syncthreads();

    const int wm = wid >> 1, wn = wid & 1;
    const bool strip_active = (m0 + wm * 32) < cnt;

    // A: 2 threads/row, cp.async from fp16 g_x16; 64 cols/chunk as 2 sub-tiles
    const int arow = tid >> 1;
    const int aent = sEnt[arow];
    const __half* axg = g_x16 + (size_t)(aent >= 0 ? (aent >> 3) : 0) * HDIM + (tid & 1) * 16;
    const uint32_t aoff = (uint32_t)(arow * 80 + (tid & 1) * 32);

    // B: 8 threads/row over 32 rows per half
    const int brow = tid >> 3, bcol = (tid & 7) * 8;
    const float* pg = wg + (size_t)e * HDIM * IDIM + n0 + bcol;
    const float* pu = wu + (size_t)e * HDIM * IDIM + n0 + bcol;

    auto cpaA = [&](int c, int s) {
        const uint32_t base = sb + META + s * A_SLOT + aoff;
        if (aent >= 0) {
            const __half* src = axg + c * 64;
            cpa16(base,               src,      16u);
            cpa16(base + 16,          src + 8,  16u);
            cpa16(base + A_SUB,       src + 32, 16u);
            cpa16(base + A_SUB + 16,  src + 40, 16u);
        } else if (c < 3) {
            cpa16(base,              axg, 0u);
            cpa16(base + 16,         axg, 0u);
            cpa16(base + A_SUB,      axg, 0u);
            cpa16(base + A_SUB + 16, axg, 0u);
        }
    };

    float4 fG[2], fU[2];
    auto loadB = [&](int k0, int h) {
        const int r = h * 32 + brow;
        const float* gp = pg + (size_t)(k0 + r) * IDIM;
        const float* up = pu + (size_t)(k0 + r) * IDIM;
        fG[0] = *(const float4*)gp; fG[1] = *(const float4*)(gp + 4);
        fU[0] = *(const float4*)up; fU[1] = *(const float4*)(up + 4);
    };
    auto stsB = [&](int b, int h) {
        const uint32_t Bg = sb + GU_B_OFF + b * GU_B_BUF;
        const uint32_t Bu = Bg + 9216;
        const uint32_t off = (uint32_t)((h * 32 + brow) * 144 + bcol * 2);
        uint32_t h0, h1, h2, h3;
        cvt2h(fG[0], h0, h1); cvt2h(fG[1], h2, h3);
        sts128(Bg + off, h0, h1, h2, h3);
        cvt2h(fU[0], h0, h1); cvt2h(fU[1], h2, h3);
        sts128(Bu + off, h0, h1, h2, h3);
    };

    float accg[2][4][4], accu[2][4][4];
#pragma unroll
    for (int i = 0; i < 2; i++)
#pragma unroll
        for (int j = 0; j < 4; j++)
#pragma unroll
            for (int q = 0; q < 4; q++) { accg[i][j][q] = 0.f; accu[i][j][q] = 0.f; }

    auto computeK = [&](int sa, int sbuf, int kklo, int kkhi) {
        const uint32_t Ab = sb + META + sa * A_SLOT;
        const uint32_t Bg = sb + GU_B_OFF + sbuf * GU_B_BUF;
        const uint32_t Bu = Bg + 9216;
#pragma unroll
        for (int kk = kklo; kk < kkhi; kk++) {
            const uint32_t Ah = Ab + (kk >> 1) * A_SUB;
            uint32_t ah[2][4];
            const uint32_t acol = ((kk & 1) * 16 + (lane >> 4) * 8) * 2;
#pragma unroll
            for (int i = 0; i < 2; i++) {
                uint32_t ra = (wm * 32 + i * 16 + (lane & 15)) * 80 + acol;
                ldsm4(ah[i][0], ah[i][1], ah[i][2], ah[i][3], Ah + ra);
            }
            const uint32_t brow_ = kk * 16 + ((lane >> 3) & 1) * 8 + (lane & 7);
#pragma unroll
            for (int hf = 0; hf < 2; hf++) {
                const uint32_t rb = brow_ * 144 + (wn * 32 + hf * 16 + (lane >> 4) * 8) * 2;
                uint32_t g0, g1, g2, g3;
                ldsm4t(g0, g1, g2, g3, Bg + rb);
#pragma unroll
                for (int i = 0; i < 2; i++) {
                    float* c0 = accg[i][hf * 2 + 0];
                    float* c1 = accg[i][hf * 2 + 1];
                    mma_h(c0[0], c0[1], c0[2], c0[3], ah[i][0], ah[i][1], ah[i][2], ah[i][3], g0, g1);
                    mma_h(c1[0], c1[1], c1[2], c1[3], ah[i][0], ah[i][1], ah[i][2], ah[i][3], g2, g3);
                }
                uint32_t u0, u1, u2, u3;
                ldsm4t(u0, u1, u2, u3, Bu + rb);
#pragma unroll
                for (int i = 0; i < 2; i++) {
                    float* c0 = accu[i][hf * 2 + 0];
                    float* c1 = accu[i][hf * 2 + 1];
                    mma_h(c0[0], c0[1], c0[2], c0[3], ah[i][0], ah[i][1], ah[i][2], ah[i][3], u0, u1);
                    mma_h(c1[0], c1[1], c1[2], c1[3], ah[i][0], ah[i][1], ah[i][2], ah[i][3], u2, u3);
                }
            }
        }
    };

    const int C = HDIM / 64;   // 32
    cpaA(0, 0); CP_COMMIT();
    cpaA(1, 1); CP_COMMIT();
    loadB(0, 0); stsB(0, 0);
    loadB(0, 1); stsB(0, 1);
    CP_WAIT1();
    __syncthreads();

    for (int c = 0; c < C; c++) {
        const int k1 = (c + 1) * 64;
        if (c + 1 < C) loadB(k1, 0);
        if (c + 2 < C) { cpaA(c + 2, (c + 2) % 3); CP_COMMIT(); }
        if (strip_active) computeK(c % 3, c & 1, 0, 2);
        if (c + 1 < C) { stsB((c + 1) & 1, 0); loadB(k1, 1); }
        if (strip_active) computeK(c % 3, c & 1, 2, 4);
        if (c + 1 < C) {
            stsB((c + 1) & 1, 1);
            if (c + 2 < C) { CP_WAIT1(); } else { CP_WAIT0(); }
            __syncthreads();
        }
    }

    // epilogue: silu(g)*u*w -> fp16 plane
    if (strip_active) {
#pragma unroll
        for (int i = 0; i < 2; i++)
#pragma unroll
            for (int nt = 0; nt < 4; nt++) {
                const int r    = wm * 32 + i * 16 + (lane >> 2);
                const int cof  = n0 + wn * 32 + nt * 8 + (lane & 3) * 2;
#pragma unroll
                for (int half_ = 0; half_ < 2; half_++) {
                    const int rr  = r + half_ * 8;
                    const int ent = sEnt[rr];
                    if (ent >= 0) {
                        const float w = sW[rr];
                        float g0 = accg[i][nt][half_ * 2 + 0], g1 = accg[i][nt][half_ * 2 + 1];
                        float u0 = accu[i][nt][half_ * 2 + 0], u1 = accu[i][nt][half_ * 2 + 1];
                        float v0 = g0 / (1.f + expf(-g0)) * u0 * w;
                        float v1 = g1 / (1.f + expf(-g1)) * u1 * w;
                        *(__half2*)(g_act + (size_t)ent * IDIM + cof) =
                            __floats2half2_rn(v0, v1);
                    }
                }
            }
    }
}

// ---------------- kernel 3: down HMMA GEMM, BN=128, BK=64 ----------------
__global__ __launch_bounds__(256, 2)
void down_mma(const float* __restrict__ wd, float* __restrict__ out) {
    extern __shared__ char smem[];
    const int e   = blockIdx.z;
    const int cnt = g_count[e];
    const int m0  = blockIdx.y * 128;
    if (m0 >= cnt) return;
    const int n0  = blockIdx.x * 128;
    const int tid  = threadIdx.x;
    const int wid  = tid >> 5;
    const int lane = tid & 31;

    const uint32_t sb = smem_u32(smem);
    int* sEnt = (int*)smem;

    if (tid < 128) {
        int mi = m0 + tid;
        sEnt[tid] = (mi < cnt) ? g_entry[e * T_TOK + mi] : -1;
    }
    __syncthreads();

    const int wm = wid >> 1, wn = wid & 1;
    const bool strip_active = (m0 + wm * 32) < cnt;

    // A: cp.async from fp16 g_act; 64 cols/chunk as 2 sub-tiles
    const int arow = tid >> 1;
    const int aent = sEnt[arow];
    const __half* axg = g_act + (size_t)(aent >= 0 ? aent : 0) * IDIM + (tid & 1) * 16;
    const uint32_t aoff = (uint32_t)(arow * 80 + (tid & 1) * 32);

    // B: 8 threads/row over 32 rows per half; two 8-col segments (+0, +64)
    const int brow = tid >> 3, c8 = (tid & 7) * 8;
    const float* pb = wd + (size_t)e * IDIM * HDIM + n0 + c8;

    auto cpaA = [&](int c, int s) {
        const uint32_t base = sb + META + s * A_SLOT + aoff;
        if (aent >= 0) {
            const __half* src = axg + c * 64;
            cpa16(base,              src,      16u);
            cpa16(base + 16,         src + 8,  16u);
            cpa16(base + A_SUB,      src + 32, 16u);
            cpa16(base + A_SUB + 16, src + 40, 16u);
        } else if (c < 3) {
            cpa16(base,              axg, 0u);
            cpa16(base + 16,         axg, 0u);
            cpa16(base + A_SUB,      axg, 0u);
            cpa16(base + A_SUB + 16, axg, 0u);
        }
    };

    float4 fB[4];
    auto loadB = [&](int k0, int h) {
        const float* bp = pb + (size_t)(k0 + h * 32 + brow) * HDIM;
        fB[0] = *(const float4*)bp;        fB[1] = *(const float4*)(bp + 4);
        fB[2] = *(const float4*)(bp + 64); fB[3] = *(const float4*)(bp + 68);
    };
    auto stsB = [&](int b, int h) {
        const uint32_t Bh = sb + DN_B_OFF + b * DN_B_BUF;
        const uint32_t off = (uint32_t)((h * 32 + brow) * 272 + c8 * 2);
        uint32_t h0, h1, h2, h3;
        cvt2h(fB[0], h0, h1); cvt2h(fB[1], h2, h3);
        sts128(Bh + off, h0, h1, h2, h3);
        cvt2h(fB[2], h0, h1); cvt2h(fB[3], h2, h3);
        sts128(Bh + off + 128, h0, h1, h2, h3);
    };

    float acc[2][8][4];
#pragma unroll
    for (int i = 0; i < 2; i++)
#pragma unroll
        for (int j = 0; j < 8; j++)
#pragma unroll
            for (int q = 0; q < 4; q++) acc[i][j][q] = 0.f;

    auto computeK = [&](int sa, int sbuf, int kklo, int kkhi) {
        const uint32_t Ab = sb + META + sa * A_SLOT;
        const uint32_t Bh = sb + DN_B_OFF + sbuf * DN_B_BUF;
#pragma unroll
        for (int kk = kklo; kk < kkhi; kk++) {
            const uint32_t Ah = Ab + (kk >> 1) * A_SUB;
            uint32_t ah[2][4];
            const uint32_t acol = ((kk & 1) * 16 + (lane >> 4) * 8) * 2;
#pragma unroll
            for (int i = 0; i < 2; i++) {
                uint32_t ra = (wm * 32 + i * 16 + (lane & 15)) * 80 + acol;
                ldsm4(ah[i][0], ah[i][1], ah[i][2], ah[i][3], Ah + ra);
            }
            const uint32_t brow_ = kk * 16 + ((lane >> 3) & 1) * 8 + (lane & 7);
#pragma unroll
            for (int hf = 0; hf < 4; hf++) {
                const uint32_t rb = brow_ * 272 + (wn * 64 + hf * 16 + (lane >> 4) * 8) * 2;
                uint32_t b0, b1, b2, b3;
                ldsm4t(b0, b1, b2, b3, Bh + rb);
#pragma unroll
                for (int i = 0; i < 2; i++) {
                    float* c0 = acc[i][hf * 2 + 0];
                    float* c1 = acc[i][hf * 2 + 1];
                    mma_h(c0[0], c0[1], c0[2], c0[3], ah[i][0], ah[i][1], ah[i][2], ah[i][3], b0, b1);
                    mma_h(c1[0], c1[1], c1[2], c1[3], ah[i][0], ah[i][1], ah[i][2], ah[i][3], b2, b3);
                }
            }
        }
    };

    const int C = IDIM / 64;   // 12
    cpaA(0, 0); CP_COMMIT();
    cpaA(1, 1); CP_COMMIT();
    loadB(0, 0); stsB(0, 0);
    loadB(0, 1); stsB(0, 1);
    CP_WAIT1();
    __syncthreads();

    for (int c = 0; c < C; c++) {
        const int k1 = (c + 1) * 64;
        if (c + 1 < C) loadB(k1, 0);
        if (c + 2 < C) { cpaA(c + 2, (c + 2) % 3); CP_COMMIT(); }
        if (strip_active) computeK(c % 3, c & 1, 0, 2);
        if (c + 1 < C) { stsB((c + 1) & 1, 0); loadB(k1, 1); }
        if (strip_active) computeK(c % 3, c & 1, 2, 4);
        if (c + 1 < C) {
            stsB((c + 1) & 1, 1);
            if (c + 2 < C) { CP_WAIT1(); } else { CP_WAIT0(); }
            __syncthreads();
        }
    }

    if (strip_active) {
#pragma unroll
        for (int i = 0; i < 2; i++)
#pragma unroll
            for (int nt = 0; nt < 8; nt++) {
                const int r   = wm * 32 + i * 16 + (lane >> 2);
                const int cof = n0 + wn * 64 + nt * 8 + (lane & 3) * 2;
#pragma unroll
                for (int half_ = 0; half_ < 2; half_++) {
                    const int rr  = r + half_ * 8;
                    const int ent = sEnt[rr];
                    if (ent >= 0) {
                        float* dst = out + (size_t)(ent >> 3) * HDIM + cof;
                        atomicAdd(dst,     acc[i][nt][half_ * 2 + 0]);
                        atomicAdd(dst + 1, acc[i][nt][half_ * 2 + 1]);
                    }
                }
            }
    }
}

// ---------------- launch ----------------
extern "C" void kernel_launch(void* const* d_in, const int* in_sizes, int n_in,
                              void* d_out, int out_size) {
    const float* x  = (const float*)d_in[0];
    const float* gw = (const float*)d_in[1];
    const float* wg = (const float*)d_in[2];
    const float* wu = (const float*)d_in[3];
    const float* wd = (const float*)d_in[4];
    float* out = (float*)d_out;

    static int smem_set = 0;
    if (!smem_set) {
        cudaFuncSetAttribute(gateup_mma, cudaFuncAttributeMaxDynamicSharedMemorySize, GU_SMEM);
        cudaFuncSetAttribute(down_mma,   cudaFuncAttributeMaxDynamicSharedMemorySize, DN_SMEM);
        smem_set = 1;
    }

    cudaMemsetAsync(out, 0, (size_t)T_TOK * HDIM * sizeof(float));
    xcvt_kernel<<<T_TOK * HDIM / 2048, 256>>>(x);
    router_kernel<<<T_TOK / 16, 256>>>(x, gw);

    dim3 gu_grid(IDIM / 64, T_TOK / 128, NEXP);
    gateup_mma<<<gu_grid, 256, GU_SMEM>>>(wg, wu);

    dim3 dn_grid(HDIM / 128, T_TOK / 128, NEXP);
    down_mma<<<dn_grid, 256, DN_SMEM>>>(wd, out);
}

// round 14
// speedup vs baseline: 1.0580x; 1.0580x over previous
#include <cuda_runtime.h>
#include <cuda_fp16.h>
#include <math.h>
#include <stdint.h>

#define T_TOK 1024
#define HDIM  2048
#define NEXP  64
#define IDIM  768
#define TOPK  8

// ---------------- device scratch ----------------
__device__ int    g_count[NEXP];
__device__ int    g_entry[NEXP * T_TOK];           // token*8 + slot
__device__ float  g_wt   [NEXP * T_TOK];
__device__ __half g_act  [T_TOK * TOPK * IDIM];    // fp16 silu(g)*u*w, gathered
__device__ __half g_x16  [T_TOK * HDIM];           // fp16 copy of hidden_states

// ---------------- helpers ----------------
__device__ __forceinline__ uint32_t smem_u32(const void* p) {
    uint32_t a;
    asm("{ .reg .u64 t; cvta.to.shared.u64 t, %1; cvt.u32.u64 %0, t; }" : "=r"(a) : "l"(p));
    return a;
}
__device__ __forceinline__ void sts128(uint32_t a, uint32_t x, uint32_t y, uint32_t z, uint32_t w) {
    asm volatile("st.shared.v4.b32 [%0], {%1,%2,%3,%4};" :: "r"(a), "r"(x), "r"(y), "r"(z), "r"(w));
}
__device__ __forceinline__ void ldsm4(uint32_t& r0, uint32_t& r1, uint32_t& r2, uint32_t& r3, uint32_t a) {
    asm volatile("ldmatrix.sync.aligned.m8n8.x4.shared.b16 {%0,%1,%2,%3}, [%4];"
                 : "=r"(r0), "=r"(r1), "=r"(r2), "=r"(r3) : "r"(a));
}
__device__ __forceinline__ void ldsm4t(uint32_t& r0, uint32_t& r1, uint32_t& r2, uint32_t& r3, uint32_t a) {
    asm volatile("ldmatrix.sync.aligned.m8n8.x4.trans.shared.b16 {%0,%1,%2,%3}, [%4];"
                 : "=r"(r0), "=r"(r1), "=r"(r2), "=r"(r3) : "r"(a));
}
__device__ __forceinline__ void mma_h(float& c0, float& c1, float& c2, float& c3,
                                      uint32_t a0, uint32_t a1, uint32_t a2, uint32_t a3,
                                      uint32_t b0, uint32_t b1) {
    asm volatile("mma.sync.aligned.m16n8k16.row.col.f32.f16.f16.f32 "
                 "{%0,%1,%2,%3},{%4,%5,%6,%7},{%8,%9},{%0,%1,%2,%3};"
                 : "+f"(c0), "+f"(c1), "+f"(c2), "+f"(c3)
                 : "r"(a0), "r"(a1), "r"(a2), "r"(a3), "r"(b0), "r"(b1));
}
__device__ __forceinline__ void cvt2h(float4 f, uint32_t& h0, uint32_t& h1) {
    __half2 a = __floats2half2_rn(f.x, f.y);
    __half2 b = __floats2half2_rn(f.z, f.w);
    h0 = *(uint32_t*)&a; h1 = *(uint32_t*)&b;
}
// async copy: 16B global->shared, src-size 0 => zero-fill
__device__ __forceinline__ void cpa16(uint32_t saddr, const void* gaddr, uint32_t srcsz) {
    asm volatile("cp.async.cg.shared.global [%0], [%1], 16, %2;"
                 :: "r"(saddr), "l"(gaddr), "r"(srcsz) : "memory");
}
__device__ __forceinline__ void pref_l2(const void* gaddr) {
    asm volatile("prefetch.global.L2 [%0];" :: "l"(gaddr));
}
#define CP_COMMIT() asm volatile("cp.async.commit_group;" ::: "memory")
#define CP_WAIT0()  asm volatile("cp.async.wait_group 0;" ::: "memory")
#define CP_WAIT1()  asm volatile("cp.async.wait_group 1;" ::: "memory")

// ---------- smem geometry ----------
// A tile 128x32 fp16, row stride 40 elems (80B, ldsm conflict-free), 3 slots
// gateup B: two 32x64 fp16 tiles (g,u), row stride 72 elems (144B), 2 buffers
// down   B: one 32x128 fp16 tile, row stride 136 elems (272B), 2 buffers
#define META     2048
#define A_SLOT   10240                 // 128*80
#define GU_B_OFF (META + 3 * A_SLOT)   // 32768
#define GU_B_BUF 9216                  // 2*4608
#define GU_SMEM  (GU_B_OFF + 2 * GU_B_BUF)   // 51200
#define DN_B_OFF (META + 3 * A_SLOT)
#define DN_B_BUF 8704                  // 32*272
#define DN_SMEM  (DN_B_OFF + 2 * DN_B_BUF)   // 50176

// ---------------- kernel 1: router GEMM + top-8 + scatter + x->fp16 ----------------
__global__ __launch_bounds__(256)
void router_kernel(const float* __restrict__ x, const float* __restrict__ gw) {
    __shared__ float As[16][17];
    __shared__ float Bs[16][68];
    __shared__ float Ls[16][68];

    const int t0  = blockIdx.x * 16;
    const int tid = threadIdx.x;
    const int tx  = tid & 15;
    const int ty  = tid >> 4;

    // fused: convert this block's 16 token rows of x to fp16 (x stays hot in L1/L2)
    {
        const float* xs = x + (size_t)t0 * HDIM;
        __half* xd = g_x16 + (size_t)t0 * HDIM;
#pragma unroll
        for (int it = 0; it < 16; it++) {
            int i = (it * 256 + tid) * 8;
            float4 f0 = *(const float4*)(xs + i);
            float4 f1 = *(const float4*)(xs + i + 4);
            uint4 v;
            cvt2h(f0, v.x, v.y);
            cvt2h(f1, v.z, v.w);
            *(uint4*)(xd + i) = v;
        }
    }

    const int am = tid >> 4, ak = tid & 15;
    const int be = tid & 63, bk4 = (tid >> 6) * 4;

    float acc[4] = {0.f, 0.f, 0.f, 0.f};

    for (int k0 = 0; k0 < HDIM; k0 += 16) {
        As[ak][am] = x[(size_t)(t0 + am) * HDIM + k0 + ak];
        float4 bv = *(const float4*)(gw + (size_t)be * HDIM + k0 + bk4);
        Bs[bk4 + 0][be] = bv.x; Bs[bk4 + 1][be] = bv.y;
        Bs[bk4 + 2][be] = bv.z; Bs[bk4 + 3][be] = bv.w;
        __syncthreads();
#pragma unroll
        for (int kk = 0; kk < 16; kk++) {
            float a = As[kk][ty];
#pragma unroll
            for (int j = 0; j < 4; j++) acc[j] += a * Bs[kk][tx * 4 + j];
        }
        __syncthreads();
    }

#pragma unroll
    for (int j = 0; j < 4; j++) Ls[ty][tx * 4 + j] = acc[j];
    __syncthreads();

    if (tid < 16) {
        int   sel[TOPK];
        float sv [TOPK];
        unsigned long long mask = 0ull;
#pragma unroll
        for (int k = 0; k < TOPK; k++) {
            float best = -1e30f;
            int   be_  = 0;
            for (int e = 0; e < NEXP; e++) {
                if ((mask >> e) & 1ull) continue;
                float v = Ls[tid][e];
                if (v > best) { best = v; be_ = e; }
            }
            mask |= (1ull << be_);
            sel[k] = be_;
            sv[k]  = best;
        }
        float mx = sv[0];
        float s  = 0.f;
#pragma unroll
        for (int k = 0; k < TOPK; k++) { sv[k] = expf(sv[k] - mx); s += sv[k]; }
        float inv = 1.f / s;
#pragma unroll
        for (int k = 0; k < TOPK; k++) {
            int e   = sel[k];
            int pos = atomicAdd(&g_count[e], 1);
            g_entry[e * T_TOK + pos] = (t0 + tid) * TOPK + k;
            g_wt   [e * T_TOK + pos] = sv[k] * inv;
        }
    }
}

// ---------------- kernel 2: gate+up HMMA GEMM, 3-slot A ring + B L2 prefetch ----------------
__global__ __launch_bounds__(256, 2)
void gateup_mma(const float* __restrict__ wg,
                const float* __restrict__ wu) {
    extern __shared__ char smem[];
    const int e   = blockIdx.z;
    const int cnt = g_count[e];
    const int m0  = blockIdx.y * 128;
    if (m0 >= cnt) return;
    const int n0  = blockIdx.x * 64;
    const int tid  = threadIdx.x;
    const int wid  = tid >> 5;
    const int lane = tid & 31;

    const uint32_t sb = smem_u32(smem);
    int*   sEnt = (int*)smem;
    float* sW   = (float*)(smem + 1024);

    if (tid < 128) {
        int mi = m0 + tid;
        if (mi < cnt) { sEnt[tid] = g_entry[e * T_TOK + mi]; sW[tid] = g_wt[e * T_TOK + mi]; }
        else          { sEnt[tid] = -1;                      sW[tid] = 0.f; }
    }
    __syncthreads();

    const int wm = wid >> 1, wn = wid & 1;
    const bool strip_active = (m0 + wm * 32) < cnt;

    // A: 2 threads/row, 32B each, cp.async from fp16 g_x16, 3-deep ring
    const int arow = tid >> 1;
    const int aent = sEnt[arow];
    const __half* axg = g_x16 + (size_t)(aent >= 0 ? (aent >> 3) : 0) * HDIM + (tid & 1) * 16;
    const uint32_t aoff = (uint32_t)(arow * 80 + (tid & 1) * 32);

    // B: 8 threads/row, 32B (8 fp32) per tile per thread
    const int brow = tid >> 3, bcol = (tid & 7) * 8;
    const float* pg = wg + (size_t)e * HDIM * IDIM + n0 + bcol;
    const float* pu = wu + (size_t)e * HDIM * IDIM + n0 + bcol;
    const uint32_t b16off = (uint32_t)(brow * 144 + bcol * 2);

    auto cpaA = [&](int c, int s) {
        const uint32_t base = sb + META + s * A_SLOT + aoff;
        if (aent >= 0) {
            const __half* src = axg + c * 32;
            cpa16(base,      src,     16u);
            cpa16(base + 16, src + 8, 16u);
        } else if (c < 3) {
            cpa16(base,      axg, 0u);
            cpa16(base + 16, axg, 0u);
        }
    };
    auto prefB = [&](int k0) {
        pref_l2(pg + (size_t)(k0 + brow) * IDIM);
        pref_l2(pu + (size_t)(k0 + brow) * IDIM);
    };

    float4 fG[2], fU[2];
    auto loadB = [&](int k0) {
        const float* gp = pg + (size_t)(k0 + brow) * IDIM;
        const float* up = pu + (size_t)(k0 + brow) * IDIM;
        fG[0] = *(const float4*)gp; fG[1] = *(const float4*)(gp + 4);
        fU[0] = *(const float4*)up; fU[1] = *(const float4*)(up + 4);
    };
    auto stsB = [&](int b) {
        const uint32_t Bg = sb + GU_B_OFF + b * GU_B_BUF;
        const uint32_t Bu = Bg + 4608;
        uint32_t h0, h1, h2, h3;
        cvt2h(fG[0], h0, h1); cvt2h(fG[1], h2, h3);
        sts128(Bg + b16off, h0, h1, h2, h3);
        cvt2h(fU[0], h0, h1); cvt2h(fU[1], h2, h3);
        sts128(Bu + b16off, h0, h1, h2, h3);
    };

    float accg[2][4][4], accu[2][4][4];
#pragma unroll
    for (int i = 0; i < 2; i++)
#pragma unroll
        for (int j = 0; j < 4; j++)
#pragma unroll
            for (int q = 0; q < 4; q++) { accg[i][j][q] = 0.f; accu[i][j][q] = 0.f; }

    auto compute = [&](int sa, int sbuf) {
        const uint32_t Ah = sb + META + sa * A_SLOT;
        const uint32_t Bg = sb + GU_B_OFF + sbuf * GU_B_BUF;
        const uint32_t Bu = Bg + 4608;
#pragma unroll
        for (int kk = 0; kk < 2; kk++) {
            uint32_t ah[2][4];
            const uint32_t acol = (kk * 16 + (lane >> 4) * 8) * 2;
#pragma unroll
            for (int i = 0; i < 2; i++) {
                uint32_t ra = (wm * 32 + i * 16 + (lane & 15)) * 80 + acol;
                ldsm4(ah[i][0], ah[i][1], ah[i][2], ah[i][3], Ah + ra);
            }
            const uint32_t brow_ = kk * 16 + ((lane >> 3) & 1) * 8 + (lane & 7);
#pragma unroll
            for (int hf = 0; hf < 2; hf++) {
                const uint32_t rb = brow_ * 144 + (wn * 32 + hf * 16 + (lane >> 4) * 8) * 2;
                uint32_t g0, g1, g2, g3;
                ldsm4t(g0, g1, g2, g3, Bg + rb);
#pragma unroll
                for (int i = 0; i < 2; i++) {
                    float* c0 = accg[i][hf * 2 + 0];
                    float* c1 = accg[i][hf * 2 + 1];
                    mma_h(c0[0], c0[1], c0[2], c0[3], ah[i][0], ah[i][1], ah[i][2], ah[i][3], g0, g1);
                    mma_h(c1[0], c1[1], c1[2], c1[3], ah[i][0], ah[i][1], ah[i][2], ah[i][3], g2, g3);
                }
                uint32_t u0, u1, u2, u3;
                ldsm4t(u0, u1, u2, u3, Bu + rb);
#pragma unroll
                for (int i = 0; i < 2; i++) {
                    float* c0 = accu[i][hf * 2 + 0];
                    float* c1 = accu[i][hf * 2 + 1];
                    mma_h(c0[0], c0[1], c0[2], c0[3], ah[i][0], ah[i][1], ah[i][2], ah[i][3], u0, u1);
                    mma_h(c1[0], c1[1], c1[2], c1[3], ah[i][0], ah[i][1], ah[i][2], ah[i][3], u2, u3);
                }
            }
        }
    };

    const int C = HDIM / 32;   // 64
    cpaA(0, 0); CP_COMMIT();
    cpaA(1, 1); CP_COMMIT();
    loadB(0); stsB(0);
    prefB(32);
    CP_WAIT1();                 // A slot0 ready
    __syncthreads();

    for (int c = 0; c < C; c++) {
        if (c + 1 < C) loadB((c + 1) * 32);
        if (c + 2 < C) { cpaA(c + 2, (c + 2) % 3); CP_COMMIT(); prefB((c + 2) * 32); }
        if (strip_active) compute(c % 3, c & 1);
        if (c + 1 < C) {
            stsB((c + 1) & 1);
            if (c + 2 < C) { CP_WAIT1(); } else { CP_WAIT0(); }
            __syncthreads();
        }
    }

    // epilogue: silu(g)*u*w -> fp16 plane
    if (strip_active) {
#pragma unroll
        for (int i = 0; i < 2; i++)
#pragma unroll
            for (int nt = 0; nt < 4; nt++) {
                const int r    = wm * 32 + i * 16 + (lane >> 2);
                const int cof  = n0 + wn * 32 + nt * 8 + (lane & 3) * 2;
#pragma unroll
                for (int half_ = 0; half_ < 2; half_++) {
                    const int rr  = r + half_ * 8;
                    const int ent = sEnt[rr];
                    if (ent >= 0) {
                        const float w = sW[rr];
                        float g0 = accg[i][nt][half_ * 2 + 0], g1 = accg[i][nt][half_ * 2 + 1];
                        float u0 = accu[i][nt][half_ * 2 + 0], u1 = accu[i][nt][half_ * 2 + 1];
                        float v0 = g0 / (1.f + expf(-g0)) * u0 * w;
                        float v1 = g1 / (1.f + expf(-g1)) * u1 * w;
                        *(__half2*)(g_act + (size_t)ent * IDIM + cof) =
                            __floats2half2_rn(v0, v1);
                    }
                }
            }
    }
}

// ---------------- kernel 3: down HMMA GEMM, BN=128, 3-slot A ring + B L2 prefetch ----------------
__global__ __launch_bounds__(256, 2)
void down_mma(const float* __restrict__ wd, float* __restrict__ out) {
    extern __shared__ char smem[];
    const int e   = blockIdx.z;
    const int cnt = g_count[e];
    const int m0  = blockIdx.y * 128;
    if (m0 >= cnt) return;
    const int n0  = blockIdx.x * 128;
    const int tid  = threadIdx.x;
    const int wid  = tid >> 5;
    const int lane = tid & 31;

    const uint32_t sb = smem_u32(smem);
    int* sEnt = (int*)smem;

    if (tid < 128) {
        int mi = m0 + tid;
        sEnt[tid] = (mi < cnt) ? g_entry[e * T_TOK + mi] : -1;
    }
    __syncthreads();

    const int wm = wid >> 1, wn = wid & 1;
    const bool strip_active = (m0 + wm * 32) < cnt;

    // A: cp.async from fp16 g_act, 3-deep ring
    const int arow = tid >> 1;
    const int aent = sEnt[arow];
    const __half* axg = g_act + (size_t)(aent >= 0 ? aent : 0) * IDIM + (tid & 1) * 16;
    const uint32_t aoff = (uint32_t)(arow * 80 + (tid & 1) * 32);

    // B: 8 threads/row, two 8-col fp32 segments (+0, +64)
    const int brow = tid >> 3, c8 = (tid & 7) * 8;
    const float* pb = wd + (size_t)e * IDIM * HDIM + n0 + c8;
    const uint32_t b16off = (uint32_t)(brow * 272 + c8 * 2);

    auto cpaA = [&](int c, int s) {
        const uint32_t base = sb + META + s * A_SLOT + aoff;
        if (aent >= 0) {
            const __half* src = axg + c * 32;
            cpa16(base,      src,     16u);
            cpa16(base + 16, src + 8, 16u);
        } else if (c < 3) {
            cpa16(base,      axg, 0u);
            cpa16(base + 16, axg, 0u);
        }
    };
    auto prefB = [&](int k0) {
        const float* bp = pb + (size_t)(k0 + brow) * HDIM;
        pref_l2(bp);
        pref_l2(bp + 64);
    };

    float4 fB[4];
    auto loadB = [&](int k0) {
        const float* bp = pb + (size_t)(k0 + brow) * HDIM;
        fB[0] = *(const float4*)bp;        fB[1] = *(const float4*)(bp + 4);
        fB[2] = *(const float4*)(bp + 64); fB[3] = *(const float4*)(bp + 68);
    };
    auto stsB = [&](int b) {
        const uint32_t Bh = sb + DN_B_OFF + b * DN_B_BUF;
        uint32_t h0, h1, h2, h3;
        cvt2h(fB[0], h0, h1); cvt2h(fB[1], h2, h3);
        sts128(Bh + b16off, h0, h1, h2, h3);
        cvt2h(fB[2], h0, h1); cvt2h(fB[3], h2, h3);
        sts128(Bh + b16off + 128, h0, h1, h2, h3);
    };

    float acc[2][8][4];
#pragma unroll
    for (int i = 0; i < 2; i++)
#pragma unroll
        for (int j = 0; j < 8; j++)
#pragma unroll
            for (int q = 0; q < 4; q++) acc[i][j][q] = 0.f;

    auto compute = [&](int sa, int sbuf) {
        const uint32_t Ah = sb + META + sa * A_SLOT;
        const uint32_t Bh = sb + DN_B_OFF + sbuf * DN_B_BUF;
#pragma unroll
        for (int kk = 0; kk < 2; kk++) {
            uint32_t ah[2][4];
            const uint32_t acol = (kk * 16 + (lane >> 4) * 8) * 2;
#pragma unroll
            for (int i = 0; i < 2; i++) {
                uint32_t ra = (wm * 32 + i * 16 + (lane & 15)) * 80 + acol;
                ldsm4(ah[i][0], ah[i][1], ah[i][2], ah[i][3], Ah + ra);
            }
            const uint32_t brow_ = kk * 16 + ((lane >> 3) & 1) * 8 + (lane & 7);
#pragma unroll
            for (int hf = 0; hf < 4; hf++) {
                const uint32_t rb = brow_ * 272 + (wn * 64 + hf * 16 + (lane >> 4) * 8) * 2;
                uint32_t b0, b1, b2, b3;
                ldsm4t(b0, b1, b2, b3, Bh + rb);
#pragma unroll
                for (int i = 0; i < 2; i++) {
                    float* c0 = acc[i][hf * 2 + 0];
                    float* c1 = acc[i][hf * 2 + 1];
                    mma_h(c0[0], c0[1], c0[2], c0[3], ah[i][0], ah[i][1], ah[i][2], ah[i][3], b0, b1);
                    mma_h(c1[0], c1[1], c1[2], c1[3], ah[i][0], ah[i][1], ah[i][2], ah[i][3], b2, b3);
                }
            }
        }
    };

    const int C = IDIM / 32;   // 24
    cpaA(0, 0); CP_COMMIT();
    cpaA(1, 1); CP_COMMIT();
    loadB(0); stsB(0);
    prefB(32);
    CP_WAIT1();
    __syncthreads();

    for (int c = 0; c < C; c++) {
        if (c + 1 < C) loadB((c + 1) * 32);
        if (c + 2 < C) { cpaA(c + 2, (c + 2) % 3); CP_COMMIT(); prefB((c + 2) * 32); }
        if (strip_active) compute(c % 3, c & 1);
        if (c + 1 < C) {
            stsB((c + 1) & 1);
            if (c + 2 < C) { CP_WAIT1(); } else { CP_WAIT0(); }
            __syncthreads();
        }
    }

    if (strip_active) {
#pragma unroll
        for (int i = 0; i < 2; i++)
#pragma unroll
            for (int nt = 0; nt < 8; nt++) {
                const int r   = wm * 32 + i * 16 + (lane >> 2);
                const int cof = n0 + wn * 64 + nt * 8 + (lane & 3) * 2;
#pragma unroll
                for (int half_ = 0; half_ < 2; half_++) {
                    const int rr  = r + half_ * 8;
                    const int ent = sEnt[rr];
                    if (ent >= 0) {
                        float* dst = out + (size_t)(ent >> 3) * HDIM + cof;
                        atomicAdd(dst,     acc[i][nt][half_ * 2 + 0]);
                        atomicAdd(dst + 1, acc[i][nt][half_ * 2 + 1]);
                    }
                }
            }
    }
}

// ---------------- launch ----------------
extern "C" void kernel_launch(void* const* d_in, const int* in_sizes, int n_in,
                              void* d_out, int out_size) {
    const float* x  = (const float*)d_in[0];
    const float* gw = (const float*)d_in[1];
    const float* wg = (const float*)d_in[2];
    const float* wu = (const float*)d_in[3];
    const float* wd = (const float*)d_in[4];
    float* out = (float*)d_out;

    static void* cnt_addr = nullptr;
    static int smem_set = 0;
    if (!smem_set) {
        cudaFuncSetAttribute(gateup_mma, cudaFuncAttributeMaxDynamicSharedMemorySize, GU_SMEM);
        cudaFuncSetAttribute(down_mma,   cudaFuncAttributeMaxDynamicSharedMemorySize, DN_SMEM);
        cudaGetSymbolAddress(&cnt_addr, g_count);
        smem_set = 1;
    }

    cudaMemsetAsync(out, 0, (size_t)T_TOK * HDIM * sizeof(float));
    cudaMemsetAsync(cnt_addr, 0, NEXP * sizeof(int));
    router_kernel<<<T_TOK / 16, 256>>>(x, gw);

    dim3 gu_grid(IDIM / 64, T_TOK / 128, NEXP);
    gateup_mma<<<gu_grid, 256, GU_SMEM>>>(wg, wu);

    dim3 dn_grid(HDIM / 128, T_TOK / 128, NEXP);
    down_mma<<<dn_grid, 256, DN_SMEM>>>(wd, out);
}

// round 15
// speedup vs baseline: 1.2151x; 1.1485x over previous
#include <cuda_runtime.h>
#include <cuda_fp16.h>
#include <math.h>
#include <stdint.h>

#define T_TOK 1024
#define HDIM  2048
#define NEXP  64
#define IDIM  768
#define TOPK  8
#define KSPLIT 8

// ---------------- device scratch ----------------
__device__ int    g_count[NEXP];
__device__ int    g_entry[NEXP * T_TOK];           // token*8 + slot
__device__ float  g_wt   [NEXP * T_TOK];
__device__ __half g_act  [T_TOK * TOPK * IDIM];    // fp16 silu(g)*u*w, gathered
__device__ __half g_x16  [T_TOK * HDIM];           // fp16 copy of hidden_states
__device__ float  g_part [KSPLIT * T_TOK * NEXP];  // router partial logits (2 MB)

// ---------------- helpers ----------------
__device__ __forceinline__ uint32_t smem_u32(const void* p) {
    uint32_t a;
    asm("{ .reg .u64 t; cvta.to.shared.u64 t, %1; cvt.u32.u64 %0, t; }" : "=r"(a) : "l"(p));
    return a;
}
__device__ __forceinline__ void sts128(uint32_t a, uint32_t x, uint32_t y, uint32_t z, uint32_t w) {
    asm volatile("st.shared.v4.b32 [%0], {%1,%2,%3,%4};" :: "r"(a), "r"(x), "r"(y), "r"(z), "r"(w));
}
__device__ __forceinline__ void ldsm4(uint32_t& r0, uint32_t& r1, uint32_t& r2, uint32_t& r3, uint32_t a) {
    asm volatile("ldmatrix.sync.aligned.m8n8.x4.shared.b16 {%0,%1,%2,%3}, [%4];"
                 : "=r"(r0), "=r"(r1), "=r"(r2), "=r"(r3) : "r"(a));
}
__device__ __forceinline__ void ldsm4t(uint32_t& r0, uint32_t& r1, uint32_t& r2, uint32_t& r3, uint32_t a) {
    asm volatile("ldmatrix.sync.aligned.m8n8.x4.trans.shared.b16 {%0,%1,%2,%3}, [%4];"
                 : "=r"(r0), "=r"(r1), "=r"(r2), "=r"(r3) : "r"(a));
}
__device__ __forceinline__ void mma_h(float& c0, float& c1, float& c2, float& c3,
                                      uint32_t a0, uint32_t a1, uint32_t a2, uint32_t a3,
                                      uint32_t b0, uint32_t b1) {
    asm volatile("mma.sync.aligned.m16n8k16.row.col.f32.f16.f16.f32 "
                 "{%0,%1,%2,%3},{%4,%5,%6,%7},{%8,%9},{%0,%1,%2,%3};"
                 : "+f"(c0), "+f"(c1), "+f"(c2), "+f"(c3)
                 : "r"(a0), "r"(a1), "r"(a2), "r"(a3), "r"(b0), "r"(b1));
}
__device__ __forceinline__ void cvt2h(float4 f, uint32_t& h0, uint32_t& h1) {
    __half2 a = __floats2half2_rn(f.x, f.y);
    __half2 b = __floats2half2_rn(f.z, f.w);
    h0 = *(uint32_t*)&a; h1 = *(uint32_t*)&b;
}
// async copy: 16B global->shared, src-size 0 => zero-fill
__device__ __forceinline__ void cpa16(uint32_t saddr, const void* gaddr, uint32_t srcsz) {
    asm volatile("cp.async.cg.shared.global [%0], [%1], 16, %2;"
                 :: "r"(saddr), "l"(gaddr), "r"(srcsz) : "memory");
}
__device__ __forceinline__ void pref_l2(const void* gaddr) {
    asm volatile("prefetch.global.L2 [%0];" :: "l"(gaddr));
}
#define CP_COMMIT() asm volatile("cp.async.commit_group;" ::: "memory")
#define CP_WAIT0()  asm volatile("cp.async.wait_group 0;" ::: "memory")
#define CP_WAIT1()  asm volatile("cp.async.wait_group 1;" ::: "memory")

// ---------- smem geometry ----------
#define META     2048
#define A_SLOT   10240                 // 128*80
#define GU_B_OFF (META + 3 * A_SLOT)   // 32768
#define GU_B_BUF 9216                  // 2*4608
#define GU_SMEM  (GU_B_OFF + 2 * GU_B_BUF)   // 51200
#define DN_B_OFF (META + 3 * A_SLOT)
#define DN_B_BUF 8704                  // 32*272
#define DN_SMEM  (DN_B_OFF + 2 * DN_B_BUF)   // 50176

// ---------------- kernel 0: x -> fp16 ----------------
__global__ __launch_bounds__(256)
void xcvt_kernel(const float* __restrict__ x) {
    int i = (blockIdx.x * 256 + threadIdx.x) * 8;
    float4 f0 = *(const float4*)(x + i);
    float4 f1 = *(const float4*)(x + i + 4);
    uint4 v;
    cvt2h(f0, v.x, v.y);
    cvt2h(f1, v.z, v.w);
    *(uint4*)(g_x16 + i) = v;
}

// ---------------- kernel 1a: router GEMM, split-K partials ----------------
// grid (T/16, KSPLIT); each block: 16 tokens x 64 experts over 256-wide K slice.
__global__ __launch_bounds__(256)
void router_gemm(const float* __restrict__ x, const float* __restrict__ gw) {
    __shared__ float As[16][17];
    __shared__ float Bs[16][68];

    const int t0  = blockIdx.x * 16;
    const int kb  = blockIdx.y * (HDIM / KSPLIT);
    const int tid = threadIdx.x;
    const int tx  = tid & 15;
    const int ty  = tid >> 4;

    const int am = tid >> 4, ak = tid & 15;
    const int be = tid & 63, bk4 = (tid >> 6) * 4;

    float acc[4] = {0.f, 0.f, 0.f, 0.f};

    for (int k0 = kb; k0 < kb + HDIM / KSPLIT; k0 += 16) {
        As[ak][am] = x[(size_t)(t0 + am) * HDIM + k0 + ak];
        float4 bv = *(const float4*)(gw + (size_t)be * HDIM + k0 + bk4);
        Bs[bk4 + 0][be] = bv.x; Bs[bk4 + 1][be] = bv.y;
        Bs[bk4 + 2][be] = bv.z; Bs[bk4 + 3][be] = bv.w;
        __syncthreads();
#pragma unroll
        for (int kk = 0; kk < 16; kk++) {
            float a = As[kk][ty];
#pragma unroll
            for (int j = 0; j < 4; j++) acc[j] += a * Bs[kk][tx * 4 + j];
        }
        __syncthreads();
    }

    float* dst = g_part + ((size_t)blockIdx.y * T_TOK + (t0 + ty)) * NEXP + tx * 4;
#pragma unroll
    for (int j = 0; j < 4; j++) dst[j] = acc[j];
}

// ---------------- kernel 1b: sum partials + top-8 + bucket scatter ----------------
__global__ __launch_bounds__(256)
void router_topk() {
    __shared__ float Ls[16][68];
    const int t0  = blockIdx.x * 16;
    const int tid = threadIdx.x;

    // 256 threads = 16 tokens x 16 expert-groups of 4
    {
        const int t = tid >> 4, e4 = (tid & 15) * 4;
        float s0 = 0.f, s1 = 0.f, s2 = 0.f, s3 = 0.f;
#pragma unroll
        for (int ks = 0; ks < KSPLIT; ks++) {
            const float* p = g_part + ((size_t)ks * T_TOK + (t0 + t)) * NEXP + e4;
            float4 v = *(const float4*)p;
            s0 += v.x; s1 += v.y; s2 += v.z; s3 += v.w;
        }
        Ls[t][e4 + 0] = s0; Ls[t][e4 + 1] = s1;
        Ls[t][e4 + 2] = s2; Ls[t][e4 + 3] = s3;
    }
    __syncthreads();

    if (tid < 16) {
        int   sel[TOPK];
        float sv [TOPK];
        unsigned long long mask = 0ull;
#pragma unroll
        for (int k = 0; k < TOPK; k++) {
            float best = -1e30f;
            int   be_  = 0;
            for (int e = 0; e < NEXP; e++) {
                if ((mask >> e) & 1ull) continue;
                float v = Ls[tid][e];
                if (v > best) { best = v; be_ = e; }
            }
            mask |= (1ull << be_);
            sel[k] = be_;
            sv[k]  = best;
        }
        float mx = sv[0];
        float s  = 0.f;
#pragma unroll
        for (int k = 0; k < TOPK; k++) { sv[k] = expf(sv[k] - mx); s += sv[k]; }
        float inv = 1.f / s;
#pragma unroll
        for (int k = 0; k < TOPK; k++) {
            int e   = sel[k];
            int pos = atomicAdd(&g_count[e], 1);
            g_entry[e * T_TOK + pos] = (t0 + tid) * TOPK + k;
            g_wt   [e * T_TOK + pos] = sv[k] * inv;
        }
    }
}

// ---------------- kernel 2: gate+up HMMA GEMM, 3-slot A ring + B L2 prefetch ----------------
__global__ __launch_bounds__(256, 2)
void gateup_mma(const float* __restrict__ wg,
                const float* __restrict__ wu) {
    extern __shared__ char smem[];
    const int e   = blockIdx.z;
    const int cnt = g_count[e];
    const int m0  = blockIdx.y * 128;
    if (m0 >= cnt) return;
    const int n0  = blockIdx.x * 64;
    const int tid  = threadIdx.x;
    const int wid  = tid >> 5;
    const int lane = tid & 31;

    const uint32_t sb = smem_u32(smem);
    int*   sEnt = (int*)smem;
    float* sW   = (float*)(smem + 1024);

    if (tid < 128) {
        int mi = m0 + tid;
        if (mi < cnt) { sEnt[tid] = g_entry[e * T_TOK + mi]; sW[tid] = g_wt[e * T_TOK + mi]; }
        else          { sEnt[tid] = -1;                      sW[tid] = 0.f; }
    }
    __syncthreads();

    const int wm = wid >> 1, wn = wid & 1;
    const bool strip_active = (m0 + wm * 32) < cnt;

    const int arow = tid >> 1;
    const int aent = sEnt[arow];
    const __half* axg = g_x16 + (size_t)(aent >= 0 ? (aent >> 3) : 0) * HDIM + (tid & 1) * 16;
    const uint32_t aoff = (uint32_t)(arow * 80 + (tid & 1) * 32);

    const int brow = tid >> 3, bcol = (tid & 7) * 8;
    const float* pg = wg + (size_t)e * HDIM * IDIM + n0 + bcol;
    const float* pu = wu + (size_t)e * HDIM * IDIM + n0 + bcol;
    const uint32_t b16off = (uint32_t)(brow * 144 + bcol * 2);

    auto cpaA = [&](int c, int s) {
        const uint32_t base = sb + META + s * A_SLOT + aoff;
        if (aent >= 0) {
            const __half* src = axg + c * 32;
            cpa16(base,      src,     16u);
            cpa16(base + 16, src + 8, 16u);
        } else if (c < 3) {
            cpa16(base,      axg, 0u);
            cpa16(base + 16, axg, 0u);
        }
    };
    auto prefB = [&](int k0) {
        pref_l2(pg + (size_t)(k0 + brow) * IDIM);
        pref_l2(pu + (size_t)(k0 + brow) * IDIM);
    };

    float4 fG[2], fU[2];
    auto loadB = [&](int k0) {
        const float* gp = pg + (size_t)(k0 + brow) * IDIM;
        const float* up = pu + (size_t)(k0 + brow) * IDIM;
        fG[0] = *(const float4*)gp; fG[1] = *(const float4*)(gp + 4);
        fU[0] = *(const float4*)up; fU[1] = *(const float4*)(up + 4);
    };
    auto stsB = [&](int b) {
        const uint32_t Bg = sb + GU_B_OFF + b * GU_B_BUF;
        const uint32_t Bu = Bg + 4608;
        uint32_t h0, h1, h2, h3;
        cvt2h(fG[0], h0, h1); cvt2h(fG[1], h2, h3);
        sts128(Bg + b16off, h0, h1, h2, h3);
        cvt2h(fU[0], h0, h1); cvt2h(fU[1], h2, h3);
        sts128(Bu + b16off, h0, h1, h2, h3);
    };

    float accg[2][4][4], accu[2][4][4];
#pragma unroll
    for (int i = 0; i < 2; i++)
#pragma unroll
        for (int j = 0; j < 4; j++)
#pragma unroll
            for (int q = 0; q < 4; q++) { accg[i][j][q] = 0.f; accu[i][j][q] = 0.f; }

    auto compute = [&](int sa, int sbuf) {
        const uint32_t Ah = sb + META + sa * A_SLOT;
        const uint32_t Bg = sb + GU_B_OFF + sbuf * GU_B_BUF;
        const uint32_t Bu = Bg + 4608;
#pragma unroll
        for (int kk = 0; kk < 2; kk++) {
            uint32_t ah[2][4];
            const uint32_t acol = (kk * 16 + (lane >> 4) * 8) * 2;
#pragma unroll
            for (int i = 0; i < 2; i++) {
                uint32_t ra = (wm * 32 + i * 16 + (lane & 15)) * 80 + acol;
                ldsm4(ah[i][0], ah[i][1], ah[i][2], ah[i][3], Ah + ra);
            }
            const uint32_t brow_ = kk * 16 + ((lane >> 3) & 1) * 8 + (lane & 7);
#pragma unroll
            for (int hf = 0; hf < 2; hf++) {
                const uint32_t rb = brow_ * 144 + (wn * 32 + hf * 16 + (lane >> 4) * 8) * 2;
                uint32_t g0, g1, g2, g3;
                ldsm4t(g0, g1, g2, g3, Bg + rb);
#pragma unroll
                for (int i = 0; i < 2; i++) {
                    float* c0 = accg[i][hf * 2 + 0];
                    float* c1 = accg[i][hf * 2 + 1];
                    mma_h(c0[0], c0[1], c0[2], c0[3], ah[i][0], ah[i][1], ah[i][2], ah[i][3], g0, g1);
                    mma_h(c1[0], c1[1], c1[2], c1[3], ah[i][0], ah[i][1], ah[i][2], ah[i][3], g2, g3);
                }
                uint32_t u0, u1, u2, u3;
                ldsm4t(u0, u1, u2, u3, Bu + rb);
#pragma unroll
                for (int i = 0; i < 2; i++) {
                    float* c0 = accu[i][hf * 2 + 0];
                    float* c1 = accu[i][hf * 2 + 1];
                    mma_h(c0[0], c0[1], c0[2], c0[3], ah[i][0], ah[i][1], ah[i][2], ah[i][3], u0, u1);
                    mma_h(c1[0], c1[1], c1[2], c1[3], ah[i][0], ah[i][1], ah[i][2], ah[i][3], u2, u3);
                }
            }
        }
    };

    const int C = HDIM / 32;   // 64
    cpaA(0, 0); CP_COMMIT();
    cpaA(1, 1); CP_COMMIT();
    loadB(0); stsB(0);
    prefB(32);
    CP_WAIT1();
    __syncthreads();

    for (int c = 0; c < C; c++) {
        if (c + 1 < C) loadB((c + 1) * 32);
        if (c + 2 < C) { cpaA(c + 2, (c + 2) % 3); CP_COMMIT(); prefB((c + 2) * 32); }
        if (strip_active) compute(c % 3, c & 1);
        if (c + 1 < C) {
            stsB((c + 1) & 1);
            if (c + 2 < C) { CP_WAIT1(); } else { CP_WAIT0(); }
            __syncthreads();
        }
    }

    if (strip_active) {
#pragma unroll
        for (int i = 0; i < 2; i++)
#pragma unroll
            for (int nt = 0; nt < 4; nt++) {
                const int r    = wm * 32 + i * 16 + (lane >> 2);
                const int cof  = n0 + wn * 32 + nt * 8 + (lane & 3) * 2;
#pragma unroll
                for (int half_ = 0; half_ < 2; half_++) {
                    const int rr  = r + half_ * 8;
                    const int ent = sEnt[rr];
                    if (ent >= 0) {
                        const float w = sW[rr];
                        float g0 = accg[i][nt][half_ * 2 + 0], g1 = accg[i][nt][half_ * 2 + 1];
                        float u0 = accu[i][nt][half_ * 2 + 0], u1 = accu[i][nt][half_ * 2 + 1];
                        float v0 = g0 / (1.f + expf(-g0)) * u0 * w;
                        float v1 = g1 / (1.f + expf(-g1)) * u1 * w;
                        *(__half2*)(g_act + (size_t)ent * IDIM + cof) =
                            __floats2half2_rn(v0, v1);
                    }
                }
            }
    }
}

// ---------------- kernel 3: down HMMA GEMM, BN=128, 3-slot A ring + B L2 prefetch ----------------
__global__ __launch_bounds__(256, 2)
void down_mma(const float* __restrict__ wd, float* __restrict__ out) {
    extern __shared__ char smem[];
    const int e   = blockIdx.z;
    const int cnt = g_count[e];
    const int m0  = blockIdx.y * 128;
    if (m0 >= cnt) return;
    const int n0  = blockIdx.x * 128;
    const int tid  = threadIdx.x;
    const int wid  = tid >> 5;
    const int lane = tid & 31;

    const uint32_t sb = smem_u32(smem);
    int* sEnt = (int*)smem;

    if (tid < 128) {
        int mi = m0 + tid;
        sEnt[tid] = (mi < cnt) ? g_entry[e * T_TOK + mi] : -1;
    }
    __syncthreads();

    const int wm = wid >> 1, wn = wid & 1;
    const bool strip_active = (m0 + wm * 32) < cnt;

    const int arow = tid >> 1;
    const int aent = sEnt[arow];
    const __half* axg = g_act + (size_t)(aent >= 0 ? aent : 0) * IDIM + (tid & 1) * 16;
    const uint32_t aoff = (uint32_t)(arow * 80 + (tid & 1) * 32);

    const int brow = tid >> 3, c8 = (tid & 7) * 8;
    const float* pb = wd + (size_t)e * IDIM * HDIM + n0 + c8;
    const uint32_t b16off = (uint32_t)(brow * 272 + c8 * 2);

    auto cpaA = [&](int c, int s) {
        const uint32_t base = sb + META + s * A_SLOT + aoff;
        if (aent >= 0) {
            const __half* src = axg + c * 32;
            cpa16(base,      src,     16u);
            cpa16(base + 16, src + 8, 16u);
        } else if (c < 3) {
            cpa16(base,      axg, 0u);
            cpa16(base + 16, axg, 0u);
        }
    };
    auto prefB = [&](int k0) {
        const float* bp = pb + (size_t)(k0 + brow) * HDIM;
        pref_l2(bp);
        pref_l2(bp + 64);
    };

    float4 fB[4];
    auto loadB = [&](int k0) {
        const float* bp = pb + (size_t)(k0 + brow) * HDIM;
        fB[0] = *(const float4*)bp;        fB[1] = *(const float4*)(bp + 4);
        fB[2] = *(const float4*)(bp + 64); fB[3] = *(const float4*)(bp + 68);
    };
    auto stsB = [&](int b) {
        const uint32_t Bh = sb + DN_B_OFF + b * DN_B_BUF;
        uint32_t h0, h1, h2, h3;
        cvt2h(fB[0], h0, h1); cvt2h(fB[1], h2, h3);
        sts128(Bh + b16off, h0, h1, h2, h3);
        cvt2h(fB[2], h0, h1); cvt2h(fB[3], h2, h3);
        sts128(Bh + b16off + 128, h0, h1, h2, h3);
    };

    float acc[2][8][4];
#pragma unroll
    for (int i = 0; i < 2; i++)
#pragma unroll
        for (int j = 0; j < 8; j++)
#pragma unroll
            for (int q = 0; q < 4; q++) acc[i][j][q] = 0.f;

    auto compute = [&](int sa, int sbuf) {
        const uint32_t Ah = sb + META + sa * A_SLOT;
        const uint32_t Bh = sb + DN_B_OFF + sbuf * DN_B_BUF;
#pragma unroll
        for (int kk = 0; kk < 2; kk++) {
            uint32_t ah[2][4];
            const uint32_t acol = (kk * 16 + (lane >> 4) * 8) * 2;
#pragma unroll
            for (int i = 0; i < 2; i++) {
                uint32_t ra = (wm * 32 + i * 16 + (lane & 15)) * 80 + acol;
                ldsm4(ah[i][0], ah[i][1], ah[i][2], ah[i][3], Ah + ra);
            }
            const uint32_t brow_ = kk * 16 + ((lane >> 3) & 1) * 8 + (lane & 7);
#pragma unroll
            for (int hf = 0; hf < 4; hf++) {
                const uint32_t rb = brow_ * 272 + (wn * 64 + hf * 16 + (lane >> 4) * 8) * 2;
                uint32_t b0, b1, b2, b3;
                ldsm4t(b0, b1, b2, b3, Bh + rb);
#pragma unroll
                for (int i = 0; i < 2; i++) {
                    float* c0 = acc[i][hf * 2 + 0];
                    float* c1 = acc[i][hf * 2 + 1];
                    mma_h(c0[0], c0[1], c0[2], c0[3], ah[i][0], ah[i][1], ah[i][2], ah[i][3], b0, b1);
                    mma_h(c1[0], c1[1], c1[2], c1[3], ah[i][0], ah[i][1], ah[i][2], ah[i][3], b2, b3);
                }
            }
        }
    };

    const int C = IDIM / 32;   // 24
    cpaA(0, 0); CP_COMMIT();
    cpaA(1, 1); CP_COMMIT();
    loadB(0); stsB(0);
    prefB(32);
    CP_WAIT1();
    __syncthreads();

    for (int c = 0; c < C; c++) {
        if (c + 1 < C) loadB((c + 1) * 32);
        if (c + 2 < C) { cpaA(c + 2, (c + 2) % 3); CP_COMMIT(); prefB((c + 2) * 32); }
        if (strip_active) compute(c % 3, c & 1);
        if (c + 1 < C) {
            stsB((c + 1) & 1);
            if (c + 2 < C) { CP_WAIT1(); } else { CP_WAIT0(); }
            __syncthreads();
        }
    }

    if (strip_active) {
#pragma unroll
        for (int i = 0; i < 2; i++)
#pragma unroll
            for (int nt = 0; nt < 8; nt++) {
                const int r   = wm * 32 + i * 16 + (lane >> 2);
                const int cof = n0 + wn * 64 + nt * 8 + (lane & 3) * 2;
#pragma unroll
                for (int half_ = 0; half_ < 2; half_++) {
                    const int rr  = r + half_ * 8;
                    const int ent = sEnt[rr];
                    if (ent >= 0) {
                        float* dst = out + (size_t)(ent >> 3) * HDIM + cof;
                        atomicAdd(dst,     acc[i][nt][half_ * 2 + 0]);
                        atomicAdd(dst + 1, acc[i][nt][half_ * 2 + 1]);
                    }
                }
            }
    }
}

// ---------------- launch ----------------
extern "C" void kernel_launch(void* const* d_in, const int* in_sizes, int n_in,
                              void* d_out, int out_size) {
    const float* x  = (const float*)d_in[0];
    const float* gw = (const float*)d_in[1];
    const float* wg = (const float*)d_in[2];
    const float* wu = (const float*)d_in[3];
    const float* wd = (const float*)d_in[4];
    float* out = (float*)d_out;

    static void* cnt_addr = nullptr;
    static int smem_set = 0;
    if (!smem_set) {
        cudaFuncSetAttribute(gateup_mma, cudaFuncAttributeMaxDynamicSharedMemorySize, GU_SMEM);
        cudaFuncSetAttribute(down_mma,   cudaFuncAttributeMaxDynamicSharedMemorySize, DN_SMEM);
        cudaGetSymbolAddress(&cnt_addr, g_count);
        smem_set = 1;
    }

    cudaMemsetAsync(out, 0, (size_t)T_TOK * HDIM * sizeof(float));
    cudaMemsetAsync(cnt_addr, 0, NEXP * sizeof(int));
    xcvt_kernel<<<T_TOK * HDIM / 2048, 256>>>(x);

    dim3 rg_grid(T_TOK / 16, KSPLIT);
    router_gemm<<<rg_grid, 256>>>(x, gw);
    router_topk<<<T_TOK / 16, 256>>>();

    dim3 gu_grid(IDIM / 64, T_TOK / 128, NEXP);
    gateup_mma<<<gu_grid, 256, GU_SMEM>>>(wg, wu);

    dim3 dn_grid(HDIM / 128, T_TOK / 128, NEXP);
    down_mma<<<dn_grid, 256, DN_SMEM>>>(wd, out);
}